// round 1
// baseline (speedup 1.0000x reference)
#include <cuda_runtime.h>
#include <cuda_bf16.h>
#include <cstdint>

#define N_NODES  131072
#define N_PER    1024
#define B_GRAPHS 128
#define N_EDGE   2097152
#define HID      128
#define IN_CH    14
#define K_POOL   30
#define CONV_T   26      // K_POOL - 5 + 1
#define FEAT_LEN 832     // 32 * CONV_T

// ---------------- scratch (device globals; no runtime allocation) ----------------
__device__ float g_deg[N_NODES];
__device__ float g_deginv[N_NODES];
__device__ int   g_src[N_EDGE];
__device__ int   g_dst[N_EDGE];
__device__ float g_agg[N_NODES * HID];   // reused: first N*14 for layer 1
__device__ float g_hA[N_NODES * HID];
__device__ float g_hB[N_NODES * HID];
__device__ int   g_idx64;

// ---------------- dtype detection for edge_index (int32 vs int64) ----------------
__global__ void k_detect(const unsigned int* ei) {
    // if int64 little-endian, the high word of each element is 0 (values < 2^31).
    // if int32, odd words are random src offsets in [0,1024) -> all-zero ~impossible.
    int all0 = 1;
    for (int i = 0; i < 16; i++)
        if (ei[2 * i + 1] != 0u) all0 = 0;
    g_idx64 = all0;
}

// ---------------- zero kernels ----------------
__global__ void k_zero_deg() {
    int i = blockIdx.x * blockDim.x + threadIdx.x;
    if (i < N_NODES) g_deg[i] = 0.0f;
}
__global__ void k_zero_agg(int n4) {  // zero first n4 float4s of g_agg
    int i = blockIdx.x * blockDim.x + threadIdx.x;
    if (i < n4) ((float4*)g_agg)[i] = make_float4(0.f, 0.f, 0.f, 0.f);
}

// ---------------- edge conversion + degree count ----------------
__global__ void k_convert(const void* ei) {
    int e = blockIdx.x * blockDim.x + threadIdx.x;
    if (e >= N_EDGE) return;
    int s, d;
    if (g_idx64) {
        const long long* p = (const long long*)ei;
        s = (int)p[e];
        d = (int)p[N_EDGE + e];
    } else {
        const int* p = (const int*)ei;
        s = p[e];
        d = p[N_EDGE + e];
    }
    g_src[e] = s;
    g_dst[e] = d;
    atomicAdd(&g_deg[d], 1.0f);
}

__global__ void k_deginv() {
    int i = blockIdx.x * blockDim.x + threadIdx.x;
    if (i < N_NODES) {
        float d = g_deg[i];
        g_deginv[i] = d > 0.0f ? 1.0f / d : 0.0f;
    }
}

// ---------------- layer-1 scatter (14 channels), float2 vector atomics ----------------
__global__ void k_scatter14(const float* __restrict__ x) {
    int e = blockIdx.x * blockDim.x + threadIdx.x;
    if (e >= N_EDGE) return;
    int s = g_src[e], d = g_dst[e];
    const float2* xs = (const float2*)(x + (size_t)s * IN_CH);
    float2* ag = (float2*)(g_agg + (size_t)d * IN_CH);
#pragma unroll
    for (int i = 0; i < 7; i++) {
        atomicAdd(&ag[i], xs[i]);
    }
}

// ---------------- layer-1 dense: h = relu(agg*deginv @ wl^T + b + x @ wr^T) ----------------
__global__ __launch_bounds__(128) void k_layer1(
    const float* __restrict__ x, const float* __restrict__ wl,
    const float* __restrict__ b, const float* __restrict__ wr,
    float* __restrict__ hout) {
    __shared__ float a_s[32 * IN_CH];
    __shared__ float x_s[32 * IN_CH];
    int nb = blockIdx.x * 32;
    int tid = threadIdx.x;
    for (int i = tid; i < 32 * IN_CH; i += 128) {
        int n = i / IN_CH, c = i % IN_CH;
        int row = nb + n;
        a_s[i] = g_agg[(size_t)row * IN_CH + c] * g_deginv[row];
        x_s[i] = x[(size_t)row * IN_CH + c];
    }
    __syncthreads();
    int j = tid;  // output channel
    float acc[32];
    float bj = b[j];
#pragma unroll
    for (int n = 0; n < 32; n++) acc[n] = bj;
    for (int k = 0; k < IN_CH; k++) {
        float wlv = wl[j * IN_CH + k];
        float wrv = wr[j * IN_CH + k];
#pragma unroll
        for (int n = 0; n < 32; n++)
            acc[n] += a_s[n * IN_CH + k] * wlv + x_s[n * IN_CH + k] * wrv;
    }
#pragma unroll
    for (int n = 0; n < 32; n++)
        hout[(size_t)(nb + n) * HID + j] = fmaxf(acc[n], 0.0f);
}

// ---------------- 128-ch scatter: warp per edge, float4 vector atomics ----------------
__global__ __launch_bounds__(256) void k_scatter128(const float* __restrict__ h) {
    int gtid = blockIdx.x * blockDim.x + threadIdx.x;
    int e = gtid >> 5;
    if (e >= N_EDGE) return;
    int lane = gtid & 31;
    int s = g_src[e], d = g_dst[e];
    float4 v = ((const float4*)(h + (size_t)s * HID))[lane];
    atomicAdd(((float4*)(g_agg + (size_t)d * HID)) + lane, v);
}

// ---------------- 128x128 SAGE dense: h = relu(agg*dinv @ wl^T + b + hp @ wr^T) ----------------
__global__ __launch_bounds__(128) void k_gemm(
    const float* __restrict__ hprev, const float* __restrict__ wl,
    const float* __restrict__ b, const float* __restrict__ wr,
    float* __restrict__ hout) {
    __shared__ float a_s[32 * HID];
    __shared__ float p_s[32 * HID];
    int nb = blockIdx.x * 32;
    int tid = threadIdx.x;
    // cooperative load: 1024 float4s per tile
    const float4* agg4 = (const float4*)g_agg;
    const float4* hp4  = (const float4*)hprev;
    float4* a4 = (float4*)a_s;
    float4* p4 = (float4*)p_s;
    for (int i = tid; i < 1024; i += 128) {
        int r = i >> 5;  // local node
        float dv = g_deginv[nb + r];
        float4 v = agg4[(size_t)nb * 32 + i];
        v.x *= dv; v.y *= dv; v.z *= dv; v.w *= dv;
        a4[i] = v;
        p4[i] = hp4[(size_t)nb * 32 + i];
    }
    __syncthreads();

    int j = tid;  // output channel
    float acc[32];
    float bj = b[j];
#pragma unroll
    for (int n = 0; n < 32; n++) acc[n] = bj;

    const float4* wl4 = (const float4*)(wl + j * HID);
    const float4* wr4 = (const float4*)(wr + j * HID);
    for (int kc = 0; kc < 32; kc++) {
        float4 wlv = wl4[kc];
        float4 wrv = wr4[kc];
#pragma unroll
        for (int n = 0; n < 32; n++) {
            float4 av = ((const float4*)(a_s + n * HID))[kc];
            float4 pv = ((const float4*)(p_s + n * HID))[kc];
            acc[n] += av.x * wlv.x + av.y * wlv.y + av.z * wlv.z + av.w * wlv.w
                    + pv.x * wrv.x + pv.y * wrv.y + pv.z * wrv.z + pv.w * wrv.w;
        }
    }
#pragma unroll
    for (int n = 0; n < 32; n++)
        hout[(size_t)(nb + n) * HID + j] = fmaxf(acc[n], 0.0f);
}

// ---------------- fused top-k sort pool + conv1d + lin1 + lin2 (one block per graph) --------
__global__ __launch_bounds__(256) void k_topk_head(
    const float* __restrict__ h,
    const float* __restrict__ conv_w, const float* __restrict__ conv_b,
    const float* __restrict__ lin1_w, const float* __restrict__ lin1_b,
    const float* __restrict__ lin2_w, const float* __restrict__ lin2_b,
    float* __restrict__ out) {
    __shared__ float vals[N_PER];
    __shared__ unsigned long long red[256];
    __shared__ int sel[K_POOL];
    __shared__ float top_s[K_POOL * HID];
    __shared__ float feat[FEAT_LEN];
    __shared__ float y1[HID];

    int g = blockIdx.x;
    int tid = threadIdx.x;
    size_t base = (size_t)g * N_PER;

    for (int i = tid; i < N_PER; i += 256)
        vals[i] = h[(base + i) * HID + (HID - 1)];
    __syncthreads();

    // iterative top-k: max value, ties -> lowest index (matches jax.lax.top_k)
    for (int t = 0; t < K_POOL; t++) {
        unsigned long long best = 0ull;
        for (int i = tid; i < N_PER; i += 256) {
            float v = vals[i];
            if (v >= 0.0f) {  // taken entries set to -1; live vals are >= 0 (post-relu)
                unsigned long long key =
                    ((unsigned long long)__float_as_uint(v) << 32) |
                    (unsigned long long)(0xFFFFFFFFu - (unsigned)i);
                if (key > best) best = key;
            }
        }
        red[tid] = best;
        __syncthreads();
        for (int s = 128; s > 0; s >>= 1) {
            if (tid < s && red[tid + s] > red[tid]) red[tid] = red[tid + s];
            __syncthreads();
        }
        if (tid == 0) {
            int idx = (int)(0xFFFFFFFFu - (unsigned)(red[0] & 0xFFFFFFFFull));
            sel[t] = idx;
            vals[idx] = -1.0f;
        }
        __syncthreads();
    }

    // gather top-k rows
    for (int i = tid; i < K_POOL * HID; i += 256) {
        int t = i / HID, c = i % HID;
        top_s[i] = h[(base + sel[t]) * HID + c];
    }
    __syncthreads();

    // conv1d over K dim: feat[o*26 + t] = relu(b[o] + sum_{c,tau} top[t+tau][c] * w[o][c][tau])
    for (int m = tid; m < FEAT_LEN; m += 256) {
        int o = m / CONV_T, t = m % CONV_T;
        float acc = conv_b[o];
        const float* wrow = conv_w + (size_t)o * HID * 5;
        for (int c = 0; c < HID; c++) {
            const float* w5 = wrow + c * 5;
#pragma unroll
            for (int tau = 0; tau < 5; tau++)
                acc += top_s[(t + tau) * HID + c] * w5[tau];
        }
        feat[m] = fmaxf(acc, 0.0f);
    }
    __syncthreads();

    // lin1: [832] -> [128], relu
    if (tid < HID) {
        float acc = lin1_b[tid];
        const float* wrow = lin1_w + (size_t)tid * FEAT_LEN;
        for (int k = 0; k < FEAT_LEN; k++) acc += feat[k] * wrow[k];
        y1[tid] = fmaxf(acc, 0.0f);
    }
    __syncthreads();

    // lin2: [128] -> [4]
    if (tid < 4) {
        float acc = lin2_b[tid];
        const float* wrow = lin2_w + tid * HID;
        for (int k = 0; k < HID; k++) acc += y1[k] * wrow[k];
        out[g * 4 + tid] = acc;
    }
}

// ---------------- launcher ----------------
extern "C" void kernel_launch(void* const* d_in, const int* in_sizes, int n_in,
                              void* d_out, int out_size) {
    const float* x       = (const float*)d_in[0];
    const void*  ei      = d_in[1];
    // d_in[2] = batch (unused; block structure is fixed)
    const float* w_l1    = (const float*)d_in[3];
    const float* b_l1    = (const float*)d_in[4];
    const float* w_r1    = (const float*)d_in[5];
    const float* w_l2    = (const float*)d_in[6];
    const float* b_l2    = (const float*)d_in[7];
    const float* w_r2    = (const float*)d_in[8];
    const float* w_l3    = (const float*)d_in[9];
    const float* b_l3    = (const float*)d_in[10];
    const float* w_r3    = (const float*)d_in[11];
    const float* conv_w  = (const float*)d_in[12];
    const float* conv_b  = (const float*)d_in[13];
    const float* lin1_w  = (const float*)d_in[14];
    const float* lin1_b  = (const float*)d_in[15];
    const float* lin2_w  = (const float*)d_in[16];
    const float* lin2_b  = (const float*)d_in[17];
    float* out = (float*)d_out;

    const int ZB = 256;

    // degree + edge conversion
    k_zero_deg<<<(N_NODES + ZB - 1) / ZB, ZB>>>();
    k_detect<<<1, 1>>>((const unsigned int*)ei);
    k_convert<<<(N_EDGE + ZB - 1) / ZB, ZB>>>(ei);
    k_deginv<<<(N_NODES + ZB - 1) / ZB, ZB>>>();

    // ---- layer 1 (IN_CH=14) ----
    {
        int n4 = (N_NODES * IN_CH + 3) / 4;  // 14*131072 divisible by 2; pad-safe within buffer
        k_zero_agg<<<(n4 + ZB - 1) / ZB, ZB>>>(n4);
        k_scatter14<<<(N_EDGE + ZB - 1) / ZB, ZB>>>(x);
        k_layer1<<<N_NODES / 32, 128>>>(x, w_l1, b_l1, w_r1, g_hA);
    }

    // ---- layer 2 ----
    {
        int n4 = N_NODES * HID / 4;
        k_zero_agg<<<(n4 + ZB - 1) / ZB, ZB>>>(n4);
        k_scatter128<<<(N_EDGE * 32) / 256, 256>>>(g_hA);
        k_gemm<<<N_NODES / 32, 128>>>(g_hA, w_l2, b_l2, w_r2, g_hB);
    }

    // ---- layer 3 ----
    {
        int n4 = N_NODES * HID / 4;
        k_zero_agg<<<(n4 + ZB - 1) / ZB, ZB>>>(n4);
        k_scatter128<<<(N_EDGE * 32) / 256, 256>>>(g_hB);
        k_gemm<<<N_NODES / 32, 128>>>(g_hB, w_l3, b_l3, w_r3, g_hA);
    }

    // ---- sort pool + head ----
    k_topk_head<<<B_GRAPHS, 256>>>(g_hA, conv_w, conv_b, lin1_w, lin1_b,
                                   lin2_w, lin2_b, out);
}

// round 2
// speedup vs baseline: 1.0815x; 1.0815x over previous
#include <cuda_runtime.h>
#include <cuda_bf16.h>
#include <cstdint>

#define N_NODES  131072
#define N_PER    1024
#define B_GRAPHS 128
#define N_EDGE   2097152
#define HID      128
#define IN_CH    14
#define K_POOL   30
#define CONV_T   26      // K_POOL - 5 + 1
#define FEAT_LEN 832     // 32 * CONV_T

// ---------------- scratch (device globals; no runtime allocation) ----------------
__device__ int   g_cnt[N_NODES];       // per-node in-degree
__device__ int   g_rowstart[N_NODES];  // CSR row starts
__device__ int   g_cur[N_NODES];       // fill cursors
__device__ float g_deginv[N_NODES];
__device__ int   g_csrc[N_EDGE];       // CSR source list (grouped by dst)
__device__ float g_hA[N_NODES * HID];
__device__ float g_hB[N_NODES * HID];
__device__ int   g_idx64;

// ---------------- dtype detection for edge_index (int32 vs int64) ----------------
__global__ void k_detect(const unsigned int* ei) {
    int all0 = 1;
    for (int i = 0; i < 16; i++)
        if (ei[2 * i + 1] != 0u) all0 = 0;
    g_idx64 = all0;
}

__global__ void k_zero_cnt() {
    int i = blockIdx.x * blockDim.x + threadIdx.x;
    if (i < N_NODES) g_cnt[i] = 0;
}

// count in-degree
__global__ void k_count(const void* ei) {
    int e = blockIdx.x * blockDim.x + threadIdx.x;
    if (e >= N_EDGE) return;
    int d;
    if (g_idx64) d = (int)((const long long*)ei)[N_EDGE + e];
    else         d = ((const int*)ei)[N_EDGE + e];
    atomicAdd(&g_cnt[d], 1);
}

// single-block exclusive scan over 131072 counts (1024 thr x 128 each)
__global__ __launch_bounds__(1024) void k_scan() {
    __shared__ int sums[1024];
    int t = threadIdx.x;
    int base = t * 128;
    int s = 0;
#pragma unroll 4
    for (int i = 0; i < 128; i++) s += g_cnt[base + i];
    sums[t] = s;
    __syncthreads();
    // Hillis-Steele inclusive scan
    for (int off = 1; off < 1024; off <<= 1) {
        int v = (t >= off) ? sums[t - off] : 0;
        __syncthreads();
        sums[t] += v;
        __syncthreads();
    }
    int run = (t == 0) ? 0 : sums[t - 1];
    for (int i = 0; i < 128; i++) {
        int node = base + i;
        int c = g_cnt[node];
        g_rowstart[node] = run;
        g_cur[node] = run;
        g_deginv[node] = c > 0 ? 1.0f / (float)c : 0.0f;
        run += c;
    }
}

// fill CSR src lists
__global__ void k_fill(const void* ei) {
    int e = blockIdx.x * blockDim.x + threadIdx.x;
    if (e >= N_EDGE) return;
    int s, d;
    if (g_idx64) {
        const long long* p = (const long long*)ei;
        s = (int)p[e];
        d = (int)p[N_EDGE + e];
    } else {
        const int* p = (const int*)ei;
        s = p[e];
        d = p[N_EDGE + e];
    }
    int slot = atomicAdd(&g_cur[d], 1);
    g_csrc[slot] = s;
}

// ---------------- layer 1 fused: aggregate(14ch) + dense + relu ----------------
__global__ __launch_bounds__(256) void k_layer1(
    const float* __restrict__ x, const float* __restrict__ wl,
    const float* __restrict__ b, const float* __restrict__ wr,
    float* __restrict__ hout) {
    __shared__ float a_s[32 * IN_CH];
    __shared__ float x_s[32 * IN_CH];
    int nb = blockIdx.x * 32;
    int tid = threadIdx.x;
    int warp = tid >> 5, lane = tid & 31;

    // load x rows of this block's 32 nodes
    for (int i = tid; i < 32 * IN_CH; i += 256) {
        int n = i / IN_CH, c = i % IN_CH;
        x_s[i] = x[(size_t)(nb + n) * IN_CH + c];
    }

    // aggregate: warp w handles nodes nb + w*4 .. +3, lanes < 14 own a channel
    for (int q = 0; q < 4; q++) {
        int node = nb + warp * 4 + q;
        int start = g_rowstart[node];
        int deg = g_cnt[node];
        float acc = 0.0f;
        if (lane < IN_CH) {
            for (int j = 0; j < deg; j++) {
                int s = g_csrc[start + j];  // warp-broadcast load
                acc += x[(size_t)s * IN_CH + lane];
            }
            a_s[(warp * 4 + q) * IN_CH + lane] = acc * g_deginv[node];
        }
    }
    __syncthreads();

    // dense: 256 threads, j = out channel, half selects 16 nodes
    int j = tid & 127;
    int half = tid >> 7;
    float acc[16];
    float bj = b[j];
#pragma unroll
    for (int n = 0; n < 16; n++) acc[n] = bj;
    for (int k = 0; k < IN_CH; k++) {
        float wlv = wl[j * IN_CH + k];
        float wrv = wr[j * IN_CH + k];
#pragma unroll
        for (int n = 0; n < 16; n++) {
            int nn = half * 16 + n;
            acc[n] += a_s[nn * IN_CH + k] * wlv + x_s[nn * IN_CH + k] * wrv;
        }
    }
#pragma unroll
    for (int n = 0; n < 16; n++)
        hout[(size_t)(nb + half * 16 + n) * HID + j] = fmaxf(acc[n], 0.0f);
}

// ---------------- fused SAGE layer (HID->HID): CSR aggregate + dense + relu ----------------
__global__ __launch_bounds__(256) void k_layer(
    const float* __restrict__ h, const float* __restrict__ wl,
    const float* __restrict__ b, const float* __restrict__ wr,
    float* __restrict__ hout) {
    __shared__ float a_s[32 * HID];
    __shared__ float p_s[32 * HID];
    int nb = blockIdx.x * 32;
    int tid = threadIdx.x;
    int warp = tid >> 5, lane = tid & 31;

    // load self rows (32 x 128 f32) as float4
    const float4* h4 = (const float4*)h;
    float4* p4 = (float4*)p_s;
    for (int i = tid; i < 1024; i += 256)
        p4[i] = h4[(size_t)nb * 32 + i];

    // aggregate: warp handles 4 nodes; each lane owns one float4 slot (32 x 16B = 512B row)
    for (int q = 0; q < 4; q++) {
        int node = nb + warp * 4 + q;
        int start = g_rowstart[node];
        int deg = g_cnt[node];
        float4 acc = make_float4(0.f, 0.f, 0.f, 0.f);
        for (int j = 0; j < deg; j++) {
            int s = g_csrc[start + j];  // warp-broadcast load
            float4 v = h4[(size_t)s * 32 + lane];
            acc.x += v.x; acc.y += v.y; acc.z += v.z; acc.w += v.w;
        }
        float dv = g_deginv[node];
        acc.x *= dv; acc.y *= dv; acc.z *= dv; acc.w *= dv;
        ((float4*)a_s)[(warp * 4 + q) * 32 + lane] = acc;
    }
    __syncthreads();

    // dense: j = out channel (0..127), half = node-half (16 nodes each)
    int j = tid & 127;
    int half = tid >> 7;
    float acc[16];
    float bj = b[j];
#pragma unroll
    for (int n = 0; n < 16; n++) acc[n] = bj;

    const float4* wl4 = (const float4*)(wl + j * HID);
    const float4* wr4 = (const float4*)(wr + j * HID);
    const float4* a4 = (const float4*)a_s;
    const float4* pp4 = (const float4*)p_s;
    for (int kc = 0; kc < 32; kc++) {
        float4 wlv = wl4[kc];
        float4 wrv = wr4[kc];
#pragma unroll
        for (int n = 0; n < 16; n++) {
            int nn = half * 16 + n;
            float4 av = a4[nn * 32 + kc];
            float4 pv = pp4[nn * 32 + kc];
            acc[n] += av.x * wlv.x + av.y * wlv.y + av.z * wlv.z + av.w * wlv.w
                    + pv.x * wrv.x + pv.y * wrv.y + pv.z * wrv.z + pv.w * wrv.w;
        }
    }
#pragma unroll
    for (int n = 0; n < 16; n++)
        hout[(size_t)(nb + half * 16 + n) * HID + j] = fmaxf(acc[n], 0.0f);
}

// ---------------- fused top-k sort pool + conv1d + lin1 + lin2 ----------------
__global__ __launch_bounds__(256) void k_topk_head(
    const float* __restrict__ h,
    const float* __restrict__ conv_w, const float* __restrict__ conv_b,
    const float* __restrict__ lin1_w, const float* __restrict__ lin1_b,
    const float* __restrict__ lin2_w, const float* __restrict__ lin2_b,
    float* __restrict__ out) {
    __shared__ float vals[N_PER];
    __shared__ unsigned long long red[256];
    __shared__ int sel[K_POOL];
    __shared__ float top_s[K_POOL * HID];
    __shared__ float feat[FEAT_LEN];
    __shared__ float y1[HID];

    int g = blockIdx.x;
    int tid = threadIdx.x;
    size_t base = (size_t)g * N_PER;

    for (int i = tid; i < N_PER; i += 256)
        vals[i] = h[(base + i) * HID + (HID - 1)];
    __syncthreads();

    // iterative top-k: max value, ties -> lowest index (matches jax.lax.top_k)
    for (int t = 0; t < K_POOL; t++) {
        unsigned long long best = 0ull;
        for (int i = tid; i < N_PER; i += 256) {
            float v = vals[i];
            if (v >= 0.0f) {  // taken entries set to -1; live vals are >= 0 (post-relu)
                unsigned long long key =
                    ((unsigned long long)__float_as_uint(v) << 32) |
                    (unsigned long long)(0xFFFFFFFFu - (unsigned)i);
                if (key > best) best = key;
            }
        }
        red[tid] = best;
        __syncthreads();
        for (int s = 128; s > 0; s >>= 1) {
            if (tid < s && red[tid + s] > red[tid]) red[tid] = red[tid + s];
            __syncthreads();
        }
        if (tid == 0) {
            int idx = (int)(0xFFFFFFFFu - (unsigned)(red[0] & 0xFFFFFFFFull));
            sel[t] = idx;
            vals[idx] = -1.0f;
        }
        __syncthreads();
    }

    for (int i = tid; i < K_POOL * HID; i += 256) {
        int t = i / HID, c = i % HID;
        top_s[i] = h[(base + sel[t]) * HID + c];
    }
    __syncthreads();

    // conv1d: feat[o*26 + t] = relu(b[o] + sum_{c,tau} top[t+tau][c] * w[o][c][tau])
    for (int m = tid; m < FEAT_LEN; m += 256) {
        int o = m / CONV_T, t = m % CONV_T;
        float acc = conv_b[o];
        const float* wrow = conv_w + (size_t)o * HID * 5;
        for (int c = 0; c < HID; c++) {
            const float* w5 = wrow + c * 5;
#pragma unroll
            for (int tau = 0; tau < 5; tau++)
                acc += top_s[(t + tau) * HID + c] * w5[tau];
        }
        feat[m] = fmaxf(acc, 0.0f);
    }
    __syncthreads();

    if (tid < HID) {
        float acc = lin1_b[tid];
        const float* wrow = lin1_w + (size_t)tid * FEAT_LEN;
        for (int k = 0; k < FEAT_LEN; k++) acc += feat[k] * wrow[k];
        y1[tid] = fmaxf(acc, 0.0f);
    }
    __syncthreads();

    if (tid < 4) {
        float acc = lin2_b[tid];
        const float* wrow = lin2_w + tid * HID;
        for (int k = 0; k < HID; k++) acc += y1[k] * wrow[k];
        out[g * 4 + tid] = acc;
    }
}

// ---------------- launcher ----------------
extern "C" void kernel_launch(void* const* d_in, const int* in_sizes, int n_in,
                              void* d_out, int out_size) {
    const float* x       = (const float*)d_in[0];
    const void*  ei      = d_in[1];
    // d_in[2] = batch (unused; block structure fixed)
    const float* w_l1    = (const float*)d_in[3];
    const float* b_l1    = (const float*)d_in[4];
    const float* w_r1    = (const float*)d_in[5];
    const float* w_l2    = (const float*)d_in[6];
    const float* b_l2    = (const float*)d_in[7];
    const float* w_r2    = (const float*)d_in[8];
    const float* w_l3    = (const float*)d_in[9];
    const float* b_l3    = (const float*)d_in[10];
    const float* w_r3    = (const float*)d_in[11];
    const float* conv_w  = (const float*)d_in[12];
    const float* conv_b  = (const float*)d_in[13];
    const float* lin1_w  = (const float*)d_in[14];
    const float* lin1_b  = (const float*)d_in[15];
    const float* lin2_w  = (const float*)d_in[16];
    const float* lin2_b  = (const float*)d_in[17];
    float* out = (float*)d_out;

    const int ZB = 256;

    // CSR build
    k_detect<<<1, 32>>>((const unsigned int*)ei);
    k_zero_cnt<<<(N_NODES + ZB - 1) / ZB, ZB>>>();
    k_count<<<(N_EDGE + ZB - 1) / ZB, ZB>>>(ei);
    k_scan<<<1, 1024>>>();
    k_fill<<<(N_EDGE + ZB - 1) / ZB, ZB>>>(ei);

    // 3 SAGE layers (fused aggregate + dense)
    k_layer1<<<N_NODES / 32, 256>>>(x, w_l1, b_l1, w_r1, g_hA);
    k_layer <<<N_NODES / 32, 256>>>(g_hA, w_l2, b_l2, w_r2, g_hB);
    k_layer <<<N_NODES / 32, 256>>>(g_hB, w_l3, b_l3, w_r3, g_hA);

    // sort pool + head
    k_topk_head<<<B_GRAPHS, 256>>>(g_hA, conv_w, conv_b, lin1_w, lin1_b,
                                   lin2_w, lin2_b, out);
}

// round 3
// speedup vs baseline: 1.1451x; 1.0588x over previous
#include <cuda_runtime.h>
#include <cuda_bf16.h>
#include <cstdint>

#define N_NODES  131072
#define N_PER    1024
#define B_GRAPHS 128
#define N_EDGE   2097152
#define HID      128
#define IN_CH    14
#define K_POOL   30
#define CONV_T   26
#define FEAT_LEN 832

// ---------------- scratch ----------------
__device__ int   g_cnt[N_NODES];
__device__ int   g_rowstart[N_NODES];
__device__ int   g_cur[N_NODES];
__device__ float g_deginv[N_NODES];
__device__ int   g_csrc[N_EDGE];
__device__ float g_hA[N_NODES * HID];
__device__ float g_hB[N_NODES * HID];
__device__ int   g_part[512];
__device__ int   g_partx[512];
__device__ int   g_idx64;

__global__ void k_detect(const unsigned int* ei) {
    int all0 = 1;
    for (int i = 0; i < 16; i++)
        if (ei[2 * i + 1] != 0u) all0 = 0;
    g_idx64 = all0;
}

__global__ void k_zero_cnt() {
    int i = blockIdx.x * blockDim.x + threadIdx.x;
    if (i < N_NODES) g_cnt[i] = 0;
}

__global__ void k_count(const void* ei) {
    int e = blockIdx.x * blockDim.x + threadIdx.x;
    if (e >= N_EDGE) return;
    int d;
    if (g_idx64) d = (int)((const long long*)ei)[N_EDGE + e];
    else         d = ((const int*)ei)[N_EDGE + e];
    atomicAdd(&g_cnt[d], 1);
}

// ---- 3-phase parallel exclusive scan over g_cnt ----
__global__ __launch_bounds__(256) void k_partial() {
    __shared__ int s[256];
    int t = threadIdx.x;
    s[t] = g_cnt[blockIdx.x * 256 + t];
    __syncthreads();
    for (int o = 128; o > 0; o >>= 1) {
        if (t < o) s[t] += s[t + o];
        __syncthreads();
    }
    if (t == 0) g_part[blockIdx.x] = s[0];
}

__global__ __launch_bounds__(512) void k_scanpart() {
    __shared__ int s[512];
    int t = threadIdx.x;
    s[t] = g_part[t];
    __syncthreads();
    for (int off = 1; off < 512; off <<= 1) {
        int v = (t >= off) ? s[t - off] : 0;
        __syncthreads();
        s[t] += v;
        __syncthreads();
    }
    g_partx[t] = (t == 0) ? 0 : s[t - 1];  // exclusive
}

__global__ __launch_bounds__(256) void k_rowfill() {
    __shared__ int s[256];
    int t = threadIdx.x;
    int node = blockIdx.x * 256 + t;
    int c = g_cnt[node];
    s[t] = c;
    __syncthreads();
    // inclusive Hillis-Steele
    for (int off = 1; off < 256; off <<= 1) {
        int v = (t >= off) ? s[t - off] : 0;
        __syncthreads();
        s[t] += v;
        __syncthreads();
    }
    int start = g_partx[blockIdx.x] + s[t] - c;
    g_rowstart[node] = start;
    g_cur[node] = start;
    g_deginv[node] = c > 0 ? 1.0f / (float)c : 0.0f;
}

__global__ void k_fill(const void* ei) {
    int e = blockIdx.x * blockDim.x + threadIdx.x;
    if (e >= N_EDGE) return;
    int s, d;
    if (g_idx64) {
        const long long* p = (const long long*)ei;
        s = (int)p[e];
        d = (int)p[N_EDGE + e];
    } else {
        const int* p = (const int*)ei;
        s = p[e];
        d = p[N_EDGE + e];
    }
    int slot = atomicAdd(&g_cur[d], 1);
    g_csrc[slot] = s;
}

// ---------------- layer 1 fused: aggregate(14ch) + dense + relu ----------------
__global__ __launch_bounds__(256, 6) void k_layer1(
    const float* __restrict__ x, const float* __restrict__ wl,
    const float* __restrict__ b, const float* __restrict__ wr,
    float* __restrict__ hout) {
    __shared__ float a_s[32 * IN_CH];
    __shared__ float x_s[32 * IN_CH];
    int nb = blockIdx.x * 32;
    int tid = threadIdx.x;
    int warp = tid >> 5, lane = tid & 31;

    for (int i = tid; i < 32 * IN_CH; i += 256) {
        int n = i / IN_CH, c = i % IN_CH;
        x_s[i] = x[(size_t)(nb + n) * IN_CH + c];
    }

    for (int q = 0; q < 4; q++) {
        int node = nb + warp * 4 + q;
        int start = g_rowstart[node];
        int deg = g_cnt[node];
        if (lane < IN_CH) {
            float acc = 0.0f;
            for (int j = 0; j < deg; j++) {
                int s = g_csrc[start + j];
                acc += x[(size_t)s * IN_CH + lane];
            }
            a_s[(warp * 4 + q) * IN_CH + lane] = acc * g_deginv[node];
        }
    }
    __syncthreads();

    int j = tid & 127;
    int half = tid >> 7;
    float acc[16];
    float bj = b[j];
#pragma unroll
    for (int n = 0; n < 16; n++) acc[n] = bj;
#pragma unroll 2
    for (int k = 0; k < IN_CH; k++) {
        float wlv = wl[j * IN_CH + k];
        float wrv = wr[j * IN_CH + k];
#pragma unroll
        for (int n = 0; n < 16; n++) {
            int nn = half * 16 + n;
            acc[n] += a_s[nn * IN_CH + k] * wlv + x_s[nn * IN_CH + k] * wrv;
        }
    }
#pragma unroll
    for (int n = 0; n < 16; n++)
        hout[(size_t)(nb + half * 16 + n) * HID + j] = fmaxf(acc[n], 0.0f);
}

// ---------------- fused SAGE layer: CSR aggregate + dense + relu ----------------
__global__ __launch_bounds__(256, 4) void k_layer(
    const float* __restrict__ h, const float* __restrict__ wl,
    const float* __restrict__ b, const float* __restrict__ wr,
    float* __restrict__ hout) {
    __shared__ float a_s[32 * HID];
    __shared__ float p_s[32 * HID];
    int nb = blockIdx.x * 32;
    int tid = threadIdx.x;
    int warp = tid >> 5, lane = tid & 31;

    const float4* h4 = (const float4*)h;
    float4* p4 = (float4*)p_s;
#pragma unroll
    for (int i = 0; i < 4; i++)
        p4[tid + i * 256] = h4[(size_t)nb * 32 + tid + i * 256];

    // aggregation: warp handles 4 nodes; lane owns float4 column; 2-way MLP unroll
    for (int q = 0; q < 4; q++) {
        int node = nb + warp * 4 + q;
        int start = g_rowstart[node];
        int deg = g_cnt[node];
        float4 acc0 = make_float4(0.f, 0.f, 0.f, 0.f);
        float4 acc1 = make_float4(0.f, 0.f, 0.f, 0.f);
        int j = 0;
        for (; j + 2 <= deg; j += 2) {
            int s0 = g_csrc[start + j];
            int s1 = g_csrc[start + j + 1];
            float4 v0 = h4[(size_t)s0 * 32 + lane];
            float4 v1 = h4[(size_t)s1 * 32 + lane];
            acc0.x += v0.x; acc0.y += v0.y; acc0.z += v0.z; acc0.w += v0.w;
            acc1.x += v1.x; acc1.y += v1.y; acc1.z += v1.z; acc1.w += v1.w;
        }
        if (j < deg) {
            int s0 = g_csrc[start + j];
            float4 v0 = h4[(size_t)s0 * 32 + lane];
            acc0.x += v0.x; acc0.y += v0.y; acc0.z += v0.z; acc0.w += v0.w;
        }
        float dv = g_deginv[node];
        acc0.x = (acc0.x + acc1.x) * dv;
        acc0.y = (acc0.y + acc1.y) * dv;
        acc0.z = (acc0.z + acc1.z) * dv;
        acc0.w = (acc0.w + acc1.w) * dv;
        ((float4*)a_s)[(warp * 4 + q) * 32 + lane] = acc0;
    }
    __syncthreads();

    // dense: j = out channel, half = node-half (16 nodes)
    int j = tid & 127;
    int half = tid >> 7;
    float acc[16];
    float bj = b[j];
#pragma unroll
    for (int n = 0; n < 16; n++) acc[n] = bj;

    const float4* wl4 = (const float4*)(wl + j * HID);
    const float4* wr4 = (const float4*)(wr + j * HID);
    const float4* a4 = (const float4*)(a_s + half * 16 * HID);
    const float4* pp4 = (const float4*)(p_s + half * 16 * HID);
#pragma unroll 2
    for (int kc = 0; kc < 32; kc++) {
        float4 wlv = wl4[kc];
        float4 wrv = wr4[kc];
#pragma unroll
        for (int n = 0; n < 16; n++) {
            float4 av = a4[n * 32 + kc];
            float4 pv = pp4[n * 32 + kc];
            acc[n] += av.x * wlv.x + av.y * wlv.y + av.z * wlv.z + av.w * wlv.w
                    + pv.x * wrv.x + pv.y * wrv.y + pv.z * wrv.z + pv.w * wrv.w;
        }
    }
#pragma unroll
    for (int n = 0; n < 16; n++)
        hout[(size_t)(nb + half * 16 + n) * HID + j] = fmaxf(acc[n], 0.0f);
}

// ---------------- fused top-k + conv1d + lin1 + lin2 ----------------
__global__ __launch_bounds__(256) void k_topk_head(
    const float* __restrict__ h,
    const float* __restrict__ conv_w, const float* __restrict__ conv_b,
    const float* __restrict__ lin1_w, const float* __restrict__ lin1_b,
    const float* __restrict__ lin2_w, const float* __restrict__ lin2_b,
    float* __restrict__ out) {
    __shared__ float vals[N_PER];
    __shared__ unsigned long long wred[8];
    __shared__ int sel[K_POOL];
    __shared__ float top_s[K_POOL * HID];
    __shared__ float feat[FEAT_LEN];
    __shared__ float y1[HID];

    int g = blockIdx.x;
    int tid = threadIdx.x;
    int warp = tid >> 5, lane = tid & 31;
    size_t base = (size_t)g * N_PER;

    for (int i = tid; i < N_PER; i += 256)
        vals[i] = h[(base + i) * HID + (HID - 1)];
    __syncthreads();

    // iterative top-k: (max value, min index) matches jax.lax.top_k
    for (int t = 0; t < K_POOL; t++) {
        unsigned long long best = 0ull;
        for (int i = tid; i < N_PER; i += 256) {
            float v = vals[i];
            if (v >= 0.0f) {
                unsigned long long key =
                    ((unsigned long long)__float_as_uint(v) << 32) |
                    (unsigned long long)(0xFFFFFFFFu - (unsigned)i);
                if (key > best) best = key;
            }
        }
#pragma unroll
        for (int o = 16; o > 0; o >>= 1) {
            unsigned long long other = __shfl_down_sync(0xffffffffu, best, o);
            if (other > best) best = other;
        }
        if (lane == 0) wred[warp] = best;
        __syncthreads();
        if (tid == 0) {
            unsigned long long b0 = wred[0];
#pragma unroll
            for (int w = 1; w < 8; w++)
                if (wred[w] > b0) b0 = wred[w];
            int idx = (int)(0xFFFFFFFFu - (unsigned)(b0 & 0xFFFFFFFFull));
            sel[t] = idx;
            vals[idx] = -1.0f;
        }
        __syncthreads();
    }

    for (int i = tid; i < K_POOL * HID; i += 256) {
        int t = i / HID, c = i % HID;
        top_s[i] = h[(base + sel[t]) * HID + c];
    }
    __syncthreads();

    for (int m = tid; m < FEAT_LEN; m += 256) {
        int o = m / CONV_T, t = m % CONV_T;
        float acc = conv_b[o];
        const float* wrow = conv_w + (size_t)o * HID * 5;
        for (int c = 0; c < HID; c++) {
            const float* w5 = wrow + c * 5;
#pragma unroll
            for (int tau = 0; tau < 5; tau++)
                acc += top_s[(t + tau) * HID + c] * w5[tau];
        }
        feat[m] = fmaxf(acc, 0.0f);
    }
    __syncthreads();

    if (tid < HID) {
        float acc = lin1_b[tid];
        const float* wrow = lin1_w + (size_t)tid * FEAT_LEN;
        for (int k = 0; k < FEAT_LEN; k++) acc += feat[k] * wrow[k];
        y1[tid] = fmaxf(acc, 0.0f);
    }
    __syncthreads();

    if (tid < 4) {
        float acc = lin2_b[tid];
        const float* wrow = lin2_w + tid * HID;
        for (int k = 0; k < HID; k++) acc += y1[k] * wrow[k];
        out[g * 4 + tid] = acc;
    }
}

// ---------------- launcher ----------------
extern "C" void kernel_launch(void* const* d_in, const int* in_sizes, int n_in,
                              void* d_out, int out_size) {
    const float* x       = (const float*)d_in[0];
    const void*  ei      = d_in[1];
    const float* w_l1    = (const float*)d_in[3];
    const float* b_l1    = (const float*)d_in[4];
    const float* w_r1    = (const float*)d_in[5];
    const float* w_l2    = (const float*)d_in[6];
    const float* b_l2    = (const float*)d_in[7];
    const float* w_r2    = (const float*)d_in[8];
    const float* w_l3    = (const float*)d_in[9];
    const float* b_l3    = (const float*)d_in[10];
    const float* w_r3    = (const float*)d_in[11];
    const float* conv_w  = (const float*)d_in[12];
    const float* conv_b  = (const float*)d_in[13];
    const float* lin1_w  = (const float*)d_in[14];
    const float* lin1_b  = (const float*)d_in[15];
    const float* lin2_w  = (const float*)d_in[16];
    const float* lin2_b  = (const float*)d_in[17];
    float* out = (float*)d_out;

    const int ZB = 256;

    k_detect<<<1, 32>>>((const unsigned int*)ei);
    k_zero_cnt<<<(N_NODES + ZB - 1) / ZB, ZB>>>();
    k_count<<<(N_EDGE + ZB - 1) / ZB, ZB>>>(ei);
    k_partial<<<512, 256>>>();
    k_scanpart<<<1, 512>>>();
    k_rowfill<<<512, 256>>>();
    k_fill<<<(N_EDGE + ZB - 1) / ZB, ZB>>>(ei);

    k_layer1<<<N_NODES / 32, 256>>>(x, w_l1, b_l1, w_r1, g_hA);
    k_layer <<<N_NODES / 32, 256>>>(g_hA, w_l2, b_l2, w_r2, g_hB);
    k_layer <<<N_NODES / 32, 256>>>(g_hB, w_l3, b_l3, w_r3, g_hA);

    k_topk_head<<<B_GRAPHS, 256>>>(g_hA, conv_w, conv_b, lin1_w, lin1_b,
                                   lin2_w, lin2_b, out);
}

// round 5
// speedup vs baseline: 13.9416x; 12.1749x over previous
#include <cuda_runtime.h>
#include <cuda_bf16.h>
#include <cstdint>

#define N_NODES  131072
#define N_PER    1024
#define B_GRAPHS 128
#define N_EDGE   2097152
#define HID      128
#define IN_CH    14
#define K_POOL   30
#define CONV_T   26
#define FEAT_LEN 832

// ---------------- scratch (referenced ONLY from device code) ----------------
__device__ int   g_cnt[N_NODES];
__device__ int   g_rowstart[N_NODES];
__device__ int   g_cur[N_NODES];
__device__ float g_deginv[N_NODES];
__device__ int   g_csrc[N_EDGE];
__device__ float g_hA[N_NODES * HID];
__device__ float g_hB[N_NODES * HID];
__device__ float g_wt[4 * HID * HID];     // k-major: wl2, wr2, wl3, wr3  ([k][j])
__device__ float g_wt1[2 * IN_CH * HID];  // k-major: wl1, wr1
__device__ int   g_idx64;

// ---------------- prep: zero counts + transpose weights + detect dtype ----------------
// grid = 783 blocks of 256:
//   bid <  512          : zero g_cnt
//   512 <= bid < 768    : transpose the 4 HIDxHID matrices into g_wt (k-major)
//   768 <= bid < 782    : transpose the 2 HIDxIN_CH matrices into g_wt1 (k-major)
//   bid == 782 (tid 0)  : int32/int64 detection on edge_index
__global__ __launch_bounds__(256) void k_prep(
    const unsigned int* ei,
    const float* __restrict__ wl1, const float* __restrict__ wr1,
    const float* __restrict__ wl2, const float* __restrict__ wr2,
    const float* __restrict__ wl3, const float* __restrict__ wr3) {
    int bid = blockIdx.x, tid = threadIdx.x;
    if (bid < 512) {
        g_cnt[bid * 256 + tid] = 0;
    } else if (bid < 768) {
        int t = (bid - 512) * 256 + tid;        // 0 .. 65535
        int w = t >> 14;                         // matrix 0..3
        int rem = t & 16383;                     // j*128 + k
        int j = rem >> 7, k = rem & 127;
        const float* src = (w == 0) ? wl2 : (w == 1) ? wr2 : (w == 2) ? wl3 : wr3;
        g_wt[w * HID * HID + k * HID + j] = src[rem];
    } else if (bid < 782) {
        int t = (bid - 768) * 256 + tid;        // 0 .. 3583
        if (t < 2 * IN_CH * HID) {
            int m = t / (IN_CH * HID);
            int rem = t % (IN_CH * HID);         // j*14 + k
            int j = rem / IN_CH, k = rem % IN_CH;
            const float* src = (m == 0) ? wl1 : wr1;
            g_wt1[m * IN_CH * HID + k * HID + j] = src[rem];
        }
    } else if (tid == 0) {
        int all0 = 1;
        for (int i = 0; i < 16; i++)
            if (ei[2 * i + 1] != 0u) all0 = 0;
        g_idx64 = all0;
    }
}

__global__ void k_count(const void* ei) {
    int e = blockIdx.x * blockDim.x + threadIdx.x;
    if (e >= N_EDGE) return;
    int d;
    if (g_idx64) d = (int)((const long long*)ei)[N_EDGE + e];
    else         d = ((const int*)ei)[N_EDGE + e];
    atomicAdd(&g_cnt[d], 1);
}

// rowfill with self-computed prefix: block b sums g_cnt[0..256b), then scans its 256.
__global__ __launch_bounds__(256) void k_rowfill() {
    __shared__ int s[256];
    __shared__ int sbase[256];
    int b = blockIdx.x, t = threadIdx.x;
    const int4* c4 = (const int4*)g_cnt;
    int n4 = 64 * b;
    int sum = 0;
    for (int i = t; i < n4; i += 256) {
        int4 v = c4[i];
        sum += v.x + v.y + v.z + v.w;
    }
    sbase[t] = sum;
    __syncthreads();
    for (int o = 128; o > 0; o >>= 1) {
        if (t < o) sbase[t] += sbase[t + o];
        __syncthreads();
    }
    int base = sbase[0];

    int node = b * 256 + t;
    int c = g_cnt[node];
    s[t] = c;
    __syncthreads();
    for (int off = 1; off < 256; off <<= 1) {
        int v = (t >= off) ? s[t - off] : 0;
        __syncthreads();
        s[t] += v;
        __syncthreads();
    }
    int start = base + s[t] - c;
    g_rowstart[node] = start;
    g_cur[node] = start;
    g_deginv[node] = c > 0 ? 1.0f / (float)c : 0.0f;
}

__global__ void k_fill(const void* ei) {
    int e = blockIdx.x * blockDim.x + threadIdx.x;
    if (e >= N_EDGE) return;
    int s, d;
    if (g_idx64) {
        const long long* p = (const long long*)ei;
        s = (int)p[e];
        d = (int)p[N_EDGE + e];
    } else {
        const int* p = (const int*)ei;
        s = p[e];
        d = p[N_EDGE + e];
    }
    int slot = atomicAdd(&g_cur[d], 1);
    g_csrc[slot] = s;
}

// ---------------- layer 1 fused: aggregate(14ch) + dense(k-major wt) -> g_hA --------
__global__ __launch_bounds__(256, 6) void k_layer1(
    const float* __restrict__ x, const float* __restrict__ b) {
    __shared__ float a_s[32 * IN_CH];
    __shared__ float x_s[32 * IN_CH];
    int nb = blockIdx.x * 32;
    int tid = threadIdx.x;
    int warp = tid >> 5, lane = tid & 31;

    for (int i = tid; i < 32 * IN_CH; i += 256) {
        int n = i / IN_CH, c = i % IN_CH;
        x_s[i] = x[(size_t)(nb + n) * IN_CH + c];
    }

    for (int q = 0; q < 4; q++) {
        int node = nb + warp * 4 + q;
        int start = g_rowstart[node];
        int deg = g_cnt[node];
        if (lane < IN_CH) {
            float acc = 0.0f;
            for (int j = 0; j < deg; j++) {
                int s = g_csrc[start + j];
                acc += x[(size_t)s * IN_CH + lane];
            }
            a_s[(warp * 4 + q) * IN_CH + lane] = acc * g_deginv[node];
        }
    }
    __syncthreads();

    int j = tid & 127;
    int half = tid >> 7;
    const float* wlt = g_wt1 + j;                  // [k][j]
    const float* wrt = g_wt1 + IN_CH * HID + j;
    float acc[16];
    float bj = b[j];
#pragma unroll
    for (int n = 0; n < 16; n++) acc[n] = bj;
    const float* as = a_s + half * 16 * IN_CH;
    const float* xs = x_s + half * 16 * IN_CH;
    for (int k = 0; k < IN_CH; k++) {
        float wlv = wlt[k * HID];   // coalesced across lanes
        float wrv = wrt[k * HID];
#pragma unroll
        for (int n = 0; n < 16; n++)
            acc[n] += as[n * IN_CH + k] * wlv + xs[n * IN_CH + k] * wrv;
    }
#pragma unroll
    for (int n = 0; n < 16; n++)
        g_hA[(size_t)(nb + half * 16 + n) * HID + j] = fmaxf(acc[n], 0.0f);
}

// ---------------- fused SAGE layer: CSR aggregate + dense (k-major weights) ---------
// sel=0: g_hA -> g_hB with weights g_wt[0..2*HID*HID)
// sel=1: g_hB -> g_hA with weights g_wt[2*HID*HID..)
__global__ __launch_bounds__(256, 4) void k_layer(const float* __restrict__ b, int sel) {
    __shared__ float a_s[32 * HID];
    __shared__ float p_s[32 * HID];
    int nb = blockIdx.x * 32;
    int tid = threadIdx.x;
    int warp = tid >> 5, lane = tid & 31;

    const float* h = sel ? g_hB : g_hA;
    float* hout    = sel ? g_hA : g_hB;
    const float* wbase = g_wt + sel * (2 * HID * HID);

    const float4* h4 = (const float4*)h;
    float4* p4 = (float4*)p_s;
#pragma unroll
    for (int i = 0; i < 4; i++)
        p4[tid + i * 256] = h4[(size_t)nb * 32 + tid + i * 256];

    for (int q = 0; q < 4; q++) {
        int node = nb + warp * 4 + q;
        int start = g_rowstart[node];
        int deg = g_cnt[node];
        float4 a0 = make_float4(0.f, 0.f, 0.f, 0.f);
        float4 a1 = make_float4(0.f, 0.f, 0.f, 0.f);
        float4 a2 = make_float4(0.f, 0.f, 0.f, 0.f);
        float4 a3 = make_float4(0.f, 0.f, 0.f, 0.f);
        int j = 0;
        for (; j + 4 <= deg; j += 4) {
            int s0 = g_csrc[start + j];
            int s1 = g_csrc[start + j + 1];
            int s2 = g_csrc[start + j + 2];
            int s3 = g_csrc[start + j + 3];
            float4 v0 = h4[(size_t)s0 * 32 + lane];
            float4 v1 = h4[(size_t)s1 * 32 + lane];
            float4 v2 = h4[(size_t)s2 * 32 + lane];
            float4 v3 = h4[(size_t)s3 * 32 + lane];
            a0.x += v0.x; a0.y += v0.y; a0.z += v0.z; a0.w += v0.w;
            a1.x += v1.x; a1.y += v1.y; a1.z += v1.z; a1.w += v1.w;
            a2.x += v2.x; a2.y += v2.y; a2.z += v2.z; a2.w += v2.w;
            a3.x += v3.x; a3.y += v3.y; a3.z += v3.z; a3.w += v3.w;
        }
        for (; j < deg; j++) {
            int s0 = g_csrc[start + j];
            float4 v0 = h4[(size_t)s0 * 32 + lane];
            a0.x += v0.x; a0.y += v0.y; a0.z += v0.z; a0.w += v0.w;
        }
        float dv = g_deginv[node];
        a0.x = (a0.x + a1.x + a2.x + a3.x) * dv;
        a0.y = (a0.y + a1.y + a2.y + a3.y) * dv;
        a0.z = (a0.z + a1.z + a2.z + a3.z) * dv;
        a0.w = (a0.w + a1.w + a2.w + a3.w) * dv;
        ((float4*)a_s)[(warp * 4 + q) * 32 + lane] = a0;
    }
    __syncthreads();

    // dense: thread = (j out channel, half of nodes). k-major weights -> coalesced
    // scalar LDG (1 wavefront/warp); tiles read as uniform-address float4 LDS.
    int j = tid & 127;
    int half = tid >> 7;
    const float* wlt = wbase + j;
    const float* wrt = wbase + HID * HID + j;
    float acc[16];
    float bj = b[j];
#pragma unroll
    for (int n = 0; n < 16; n++) acc[n] = bj;

    const float4* a4 = (const float4*)(a_s + half * 16 * HID);
    const float4* pp4 = (const float4*)(p_s + half * 16 * HID);
    for (int k = 0; k < HID; k += 4) {
        float wl0 = wlt[(k + 0) * HID];
        float wl1 = wlt[(k + 1) * HID];
        float wl2 = wlt[(k + 2) * HID];
        float wl3 = wlt[(k + 3) * HID];
        float wr0 = wrt[(k + 0) * HID];
        float wr1 = wrt[(k + 1) * HID];
        float wr2 = wrt[(k + 2) * HID];
        float wr3 = wrt[(k + 3) * HID];
        int kc = k >> 2;
#pragma unroll
        for (int n = 0; n < 16; n++) {
            float4 av = a4[n * 32 + kc];
            float4 pv = pp4[n * 32 + kc];
            acc[n] += av.x * wl0 + av.y * wl1 + av.z * wl2 + av.w * wl3
                    + pv.x * wr0 + pv.y * wr1 + pv.z * wr2 + pv.w * wr3;
        }
    }
#pragma unroll
    for (int n = 0; n < 16; n++)
        hout[(size_t)(nb + half * 16 + n) * HID + j] = fmaxf(acc[n], 0.0f);
}

// ---------------- fused top-k + conv1d + lin1 + lin2 (reads g_hA) ----------------
#define TS_PAD 32
__global__ __launch_bounds__(256) void k_topk_head(
    const float* __restrict__ conv_w, const float* __restrict__ conv_b,
    const float* __restrict__ lin1_w, const float* __restrict__ lin1_b,
    const float* __restrict__ lin2_w, const float* __restrict__ lin2_b,
    float* __restrict__ out) {
    __shared__ float vals[N_PER];
    __shared__ unsigned long long wred[8];
    __shared__ int sel[K_POOL];
    __shared__ float top_ts[HID * TS_PAD];  // transposed: [c][t]
    __shared__ float feat[FEAT_LEN];
    __shared__ float y1[HID];

    const float* h = g_hA;
    int g = blockIdx.x;
    int tid = threadIdx.x;
    int warp = tid >> 5, lane = tid & 31;
    size_t base = (size_t)g * N_PER;

    for (int i = tid; i < N_PER; i += 256)
        vals[i] = h[(base + i) * HID + (HID - 1)];
    __syncthreads();

    for (int t = 0; t < K_POOL; t++) {
        unsigned long long best = 0ull;
        for (int i = tid; i < N_PER; i += 256) {
            float v = vals[i];
            if (v >= 0.0f) {
                unsigned long long key =
                    ((unsigned long long)__float_as_uint(v) << 32) |
                    (unsigned long long)(0xFFFFFFFFu - (unsigned)i);
                if (key > best) best = key;
            }
        }
#pragma unroll
        for (int o = 16; o > 0; o >>= 1) {
            unsigned long long other = __shfl_down_sync(0xffffffffu, best, o);
            if (other > best) best = other;
        }
        if (lane == 0) wred[warp] = best;
        __syncthreads();
        if (tid == 0) {
            unsigned long long b0 = wred[0];
#pragma unroll
            for (int w = 1; w < 8; w++)
                if (wred[w] > b0) b0 = wred[w];
            int idx = (int)(0xFFFFFFFFu - (unsigned)(b0 & 0xFFFFFFFFull));
            sel[t] = idx;
            vals[idx] = -1.0f;
        }
        __syncthreads();
    }

    for (int i = tid; i < K_POOL * HID; i += 256) {
        int t = i / HID, c = i % HID;
        top_ts[c * TS_PAD + t] = h[(base + sel[t]) * HID + c];
    }
    __syncthreads();

    for (int m = tid; m < FEAT_LEN; m += 256) {
        int o = m / CONV_T, t = m % CONV_T;
        float acc = conv_b[o];
        const float* wrow = conv_w + (size_t)o * HID * 5;
        for (int c = 0; c < HID; c++) {
            const float* w5 = wrow + c * 5;
            const float* ts = top_ts + c * TS_PAD + t;
#pragma unroll
            for (int tau = 0; tau < 5; tau++)
                acc += ts[tau] * w5[tau];
        }
        feat[m] = fmaxf(acc, 0.0f);
    }
    __syncthreads();

    if (tid < HID) {
        float acc = lin1_b[tid];
        const float* wrow = lin1_w + (size_t)tid * FEAT_LEN;
        for (int k = 0; k < FEAT_LEN; k++) acc += feat[k] * wrow[k];
        y1[tid] = fmaxf(acc, 0.0f);
    }
    __syncthreads();

    if (tid < 4) {
        float acc = lin2_b[tid];
        const float* wrow = lin2_w + tid * HID;
        for (int k = 0; k < HID; k++) acc += y1[k] * wrow[k];
        out[g * 4 + tid] = acc;
    }
}

// ---------------- launcher (layer 2 is the 6th launch -> ncu profiles it) -----------
extern "C" void kernel_launch(void* const* d_in, const int* in_sizes, int n_in,
                              void* d_out, int out_size) {
    const float* x       = (const float*)d_in[0];
    const void*  ei      = d_in[1];
    const float* w_l1    = (const float*)d_in[3];
    const float* b_l1    = (const float*)d_in[4];
    const float* w_r1    = (const float*)d_in[5];
    const float* w_l2    = (const float*)d_in[6];
    const float* b_l2    = (const float*)d_in[7];
    const float* w_r2    = (const float*)d_in[8];
    const float* w_l3    = (const float*)d_in[9];
    const float* b_l3    = (const float*)d_in[10];
    const float* w_r3    = (const float*)d_in[11];
    const float* conv_w  = (const float*)d_in[12];
    const float* conv_b  = (const float*)d_in[13];
    const float* lin1_w  = (const float*)d_in[14];
    const float* lin1_b  = (const float*)d_in[15];
    const float* lin2_w  = (const float*)d_in[16];
    const float* lin2_b  = (const float*)d_in[17];
    float* out = (float*)d_out;

    const int ZB = 256;

    // 1: prep (zero counts + weight transpose + detect)
    k_prep<<<783, ZB>>>((const unsigned int*)ei, w_l1, w_r1, w_l2, w_r2, w_l3, w_r3);
    // 2: count
    k_count<<<(N_EDGE + ZB - 1) / ZB, ZB>>>(ei);
    // 3: rowfill (self prefix)
    k_rowfill<<<512, ZB>>>();
    // 4: fill
    k_fill<<<(N_EDGE + ZB - 1) / ZB, ZB>>>(ei);
    // 5: layer1 -> g_hA
    k_layer1<<<N_NODES / 32, 256>>>(x, b_l1);
    // 6: layer2 (g_hA -> g_hB)   <-- profiled by ncu (-s 5 -c 1)
    k_layer<<<N_NODES / 32, 256>>>(b_l2, 0);
    // 7: layer3 (g_hB -> g_hA)
    k_layer<<<N_NODES / 32, 256>>>(b_l3, 1);
    // 8: head (reads g_hA)
    k_topk_head<<<B_GRAPHS, 256>>>(conv_w, conv_b, lin1_w, lin1_b,
                                   lin2_w, lin2_b, out);
}